// round 14
// baseline (speedup 1.0000x reference)
#include <cuda_runtime.h>

// Problem constants (fixed instance: B=2048, T=2048, H=51)
#define H_  51
#define HP  52          // padded hidden
#define JP  208         // 4*HP gate count
#define RR  16          // batch rows per CTA
#define NT  416         // threads per CTA (13 warps) -> 157 regs/thread budget
#define TT  2048
#define BB  2048
#define PS  20          // smem partial stride (conflict-free for 128-bit ops)

// Repacked weights (device globals; prep kernel fills them each launch)
__device__ float g_W1p[HP*JP];   // [k][j] layer-1 W_hh
__device__ float g_W2a[HP*JP];   // [k][j] layer-2 W_ih
__device__ float g_W2b[HP*JP];   // [k][j] layer-2 W_hh
__device__ float g_b1[JP];
__device__ float g_wx[JP];
__device__ float g_b2[JP];
__device__ float g_wlin[HP];
__device__ float g_blin[1];

__global__ void prep_kernel(const float* __restrict__ W_ih1, const float* __restrict__ W_hh1,
                            const float* __restrict__ b_ih1, const float* __restrict__ b_hh1,
                            const float* __restrict__ W_ih2, const float* __restrict__ W_hh2,
                            const float* __restrict__ b_ih2, const float* __restrict__ b_hh2,
                            const float* __restrict__ W_lin, const float* __restrict__ b_lin)
{
    int stride = gridDim.x * blockDim.x;
    int i0 = blockIdx.x * blockDim.x + threadIdx.x;
    for (int idx = i0; idx < HP*JP; idx += stride) {
        int k = idx / JP, j = idx % JP;
        int g = j / HP, n = j % HP;
        bool v = (n < H_) && (k < H_);
        int ro = g*H_ + n;
        g_W1p[idx] = v ? W_hh1[ro*H_ + k] : 0.f;
        g_W2a[idx] = v ? W_ih2[ro*H_ + k] : 0.f;
        g_W2b[idx] = v ? W_hh2[ro*H_ + k] : 0.f;
    }
    for (int j = i0; j < JP; j += stride) {
        int g = j / HP, n = j % HP;
        bool v = (n < H_);
        int ro = g*H_ + n;
        g_b1[j] = v ? (b_ih1[ro] + b_hh1[ro]) : 0.f;
        g_wx[j] = v ? W_ih1[ro] : 0.f;
        g_b2[j] = v ? (b_ih2[ro] + b_hh2[ro]) : 0.f;
    }
    for (int n = i0; n < HP; n += stride) g_wlin[n] = (n < H_) ? W_lin[n] : 0.f;
    if (i0 == 0) g_blin[0] = b_lin[0];
}

// HW tanh (single MUFU op)
__device__ __forceinline__ float tanha(float x) {
    float r; asm("tanh.approx.f32 %0, %1;" : "=f"(r) : "f"(x)); return r;
}
__device__ __forceinline__ float siga(float x) {
    return fmaf(0.5f, tanha(0.5f*x), 0.5f);
}

// ---- packed f32x2 helpers (PTX-only; ptxas won't auto-fuse) ----
__device__ __forceinline__ unsigned long long pk2(float w) {
    unsigned long long r;
    asm("mov.b64 %0, {%1, %1};" : "=l"(r) : "f"(w));
    return r;
}
__device__ __forceinline__ void fma2(unsigned long long& a, unsigned long long w, unsigned long long h) {
    asm("fma.rn.f32x2 %0, %1, %2, %3;" : "=l"(a) : "l"(w), "l"(h), "l"(a));
}

__global__ __launch_bounds__(NT, 1)
void lstm_kernel(const float* __restrict__ input, float* __restrict__ out)
{
    extern __shared__ float sm[];
    float* p1  = sm;                   // 832*PS floats (phase-1 partials)
    float* p2  = p1 + 832*PS;          // 832*PS floats (phase-2 partials)
    float* h1s = p2 + 832*PS;          // HP*RR  layout [k][r]
    float* h2s = h1s + HP*RR;
    float* xs  = h2s + HP*RR;          // RR
    float* wls = xs + RR;              // HP
    float* b2s = wls + HP;             // JP

    const int tid  = threadIdx.x;
    const int row0 = blockIdx.x * RR;

    // shared (q, jp) decomposition for BOTH phases
    const int q   = tid / 104;              // 0..3
    const int jp  = tid - q*104;            // 0..103
    const int src = q >> 1;                 // phase2: 0 = W_ih2·h1, 1 = W_hh2·h2
    const int kh  = q & 1;                  // phase2 k-half
    // update tasks: cells (un, un+26), row ur — exactly 2 per thread per layer
    const int un  = tid >> 4, ur = tid & 15;

    // register-resident weights for BOTH phases
    float w1[26];                           // phase1: G=2, K=13 (k-chunk q)
#pragma unroll
    for (int kk = 0; kk < 13; kk++) {
        w1[kk]      = g_W1p[(q*13 + kk)*JP + jp];
        w1[13 + kk] = g_W1p[(q*13 + kk)*JP + jp + 104];
    }
    float w2[52];                           // phase2: G=2, K=26 (src, kh)
    {
        const float* Ws = src ? g_W2b : g_W2a;
#pragma unroll
        for (int kk = 0; kk < 26; kk++) {
            w2[kk]      = Ws[(kh*26 + kk)*JP + jp];
            w2[26 + kk] = Ws[(kh*26 + kk)*JP + jp + 104];
        }
    }
    const float bias1a = g_b1[jp],  bias1b = g_b1[jp + 104];
    const float wxa    = g_wx[jp],  wxb    = g_wx[jp + 104];
    const float blin   = g_blin[0];

    // cell state: 2 cells per layer per thread
    float c1a = 0.f, c1b = 0.f, c2a = 0.f, c2b = 0.f;

    for (int i = tid; i < HP*RR; i += NT) { h1s[i] = 0.f; h2s[i] = 0.f; }
    for (int i = tid; i < HP; i += NT) wls[i] = g_wlin[i];
    for (int i = tid; i < JP; i += NT) b2s[i] = g_b2[i];
    float x1hold = 0.f;
    if (tid >= RR && tid < 2*RR) {
        xs[tid - RR] = input[(row0 + tid - RR)*TT + 0];
        x1hold = input[(row0 + tid - RR)*TT + 1];
    }
    __syncthreads();

    // ============ prologue: phase1(0) -> update1(0), xs = x(1) ============
    {
        unsigned long long acc[16];
        if (q == 0) {
            unsigned long long bpA = pk2(bias1a), wpA = pk2(wxa);
            unsigned long long bpB = pk2(bias1b), wpB = pk2(wxb);
            const ulonglong2* xv = reinterpret_cast<const ulonglong2*>(xs);
#pragma unroll
            for (int rv = 0; rv < 4; rv++) {
                ulonglong2 x2 = xv[rv];
                acc[2*rv+0] = bpA; fma2(acc[2*rv+0], wpA, x2.x);
                acc[2*rv+1] = bpA; fma2(acc[2*rv+1], wpA, x2.y);
                acc[8+2*rv+0] = bpB; fma2(acc[8+2*rv+0], wpB, x2.x);
                acc[8+2*rv+1] = bpB; fma2(acc[8+2*rv+1], wpB, x2.y);
            }
        } else {
#pragma unroll
            for (int k = 0; k < 16; k++) acc[k] = 0ULL;
        }
        // h1(-1) = 0 -> no k-loop needed
        ulonglong2* pwA = reinterpret_cast<ulonglong2*>(p1 + (q*JP + jp)*PS);
        ulonglong2* pwB = reinterpret_cast<ulonglong2*>(p1 + (q*JP + jp + 104)*PS);
#pragma unroll
        for (int rv = 0; rv < 4; rv++) {
            ulonglong2 vA; vA.x = acc[2*rv+0];   vA.y = acc[2*rv+1];   pwA[rv] = vA;
            ulonglong2 vB; vB.x = acc[8+2*rv+0]; vB.y = acc[8+2*rv+1]; pwB[rv] = vB;
        }
    }
    __syncthreads();
    {
#pragma unroll
        for (int tsk = 0; tsk < 2; tsk++) {
            int n = un + tsk*26;
            float gi = (p1[(0*JP + 0*HP+n)*PS + ur] + p1[(1*JP + 0*HP+n)*PS + ur])
                     + (p1[(2*JP + 0*HP+n)*PS + ur] + p1[(3*JP + 0*HP+n)*PS + ur]);
            float gf = (p1[(0*JP + 1*HP+n)*PS + ur] + p1[(1*JP + 1*HP+n)*PS + ur])
                     + (p1[(2*JP + 1*HP+n)*PS + ur] + p1[(3*JP + 1*HP+n)*PS + ur]);
            float gg = (p1[(0*JP + 2*HP+n)*PS + ur] + p1[(1*JP + 2*HP+n)*PS + ur])
                     + (p1[(2*JP + 2*HP+n)*PS + ur] + p1[(3*JP + 2*HP+n)*PS + ur]);
            float go = (p1[(0*JP + 3*HP+n)*PS + ur] + p1[(1*JP + 3*HP+n)*PS + ur])
                     + (p1[(2*JP + 3*HP+n)*PS + ur] + p1[(3*JP + 3*HP+n)*PS + ur]);
            float c = tsk ? c1b : c1a;
            c = siga(gf)*c + siga(gi)*tanha(gg);
            if (tsk) c1b = c; else c1a = c;
            h1s[n*RR + ur] = siga(go)*tanha(c);
        }
    }
    if (tid >= RR && tid < 2*RR) xs[tid - RR] = x1hold;  // xs = x(1)
    __syncthreads();

    // ============ main loop: 2 barriers per step ============
    for (int i = 0; i < TT; i++) {
        float xnext = 0.f;
        if (tid >= RR && tid < 2*RR && (i + 2) < TT)
            xnext = __ldg(&input[(row0 + tid - RR)*TT + i + 2]);

        // ---- slot M: out(i-1) | phase2(i) | phase1(i+1), all in-thread ----
        if (tid < 32 && i > 0) {
            int r = tid & 15, hf = tid >> 4;
            float s = 0.f;
            const float* wb = wls + hf*26;
            const float* hb = h2s + hf*26*RR;
#pragma unroll
            for (int n = 0; n < 26; n++) s = fmaf(wb[n], hb[n*RR + r], s);
            s += __shfl_xor_sync(0xffffffffu, s, 16);
            if (hf == 0) out[(row0 + r)*TT + (i - 1)] = s + blin;
        }
        // phase2(i): G=2, K=26 -> p2
        {
            unsigned long long acc[16];
#pragma unroll
            for (int k = 0; k < 16; k++) acc[k] = 0ULL;
            const ulonglong2* hb =
                reinterpret_cast<const ulonglong2*>((src ? h2s : h1s) + kh*26*RR);
#pragma unroll
            for (int kk = 0; kk < 26; kk++) {
                unsigned long long wA = pk2(w2[kk]);
                unsigned long long wB = pk2(w2[26 + kk]);
#pragma unroll
                for (int rv = 0; rv < 4; rv++) {
                    ulonglong2 h = hb[kk*4 + rv];
                    fma2(acc[2*rv+0],   wA, h.x);
                    fma2(acc[2*rv+1],   wA, h.y);
                    fma2(acc[8+2*rv+0], wB, h.x);
                    fma2(acc[8+2*rv+1], wB, h.y);
                }
            }
            ulonglong2* pwA = reinterpret_cast<ulonglong2*>(p2 + (q*JP + jp)*PS);
            ulonglong2* pwB = reinterpret_cast<ulonglong2*>(p2 + (q*JP + jp + 104)*PS);
#pragma unroll
            for (int rv = 0; rv < 4; rv++) {
                ulonglong2 vA; vA.x = acc[2*rv+0];   vA.y = acc[2*rv+1];   pwA[rv] = vA;
                ulonglong2 vB; vB.x = acc[8+2*rv+0]; vB.y = acc[8+2*rv+1]; pwB[rv] = vB;
            }
        }
        // phase1(i+1): G=2, K=13, reads xs = x(i+1) -> p1
        {
            unsigned long long acc[16];
            if (q == 0) {
                unsigned long long bpA = pk2(bias1a), wpA = pk2(wxa);
                unsigned long long bpB = pk2(bias1b), wpB = pk2(wxb);
                const ulonglong2* xv = reinterpret_cast<const ulonglong2*>(xs);
#pragma unroll
                for (int rv = 0; rv < 4; rv++) {
                    ulonglong2 x2 = xv[rv];
                    acc[2*rv+0] = bpA; fma2(acc[2*rv+0], wpA, x2.x);
                    acc[2*rv+1] = bpA; fma2(acc[2*rv+1], wpA, x2.y);
                    acc[8+2*rv+0] = bpB; fma2(acc[8+2*rv+0], wpB, x2.x);
                    acc[8+2*rv+1] = bpB; fma2(acc[8+2*rv+1], wpB, x2.y);
                }
            } else {
#pragma unroll
                for (int k = 0; k < 16; k++) acc[k] = 0ULL;
            }
            const ulonglong2* hb = reinterpret_cast<const ulonglong2*>(h1s + q*13*RR);
#pragma unroll
            for (int kk = 0; kk < 13; kk++) {
                unsigned long long wA = pk2(w1[kk]);
                unsigned long long wB = pk2(w1[13 + kk]);
#pragma unroll
                for (int rv = 0; rv < 4; rv++) {
                    ulonglong2 h = hb[kk*4 + rv];
                    fma2(acc[2*rv+0],   wA, h.x);
                    fma2(acc[2*rv+1],   wA, h.y);
                    fma2(acc[8+2*rv+0], wB, h.x);
                    fma2(acc[8+2*rv+1], wB, h.y);
                }
            }
            ulonglong2* pwA = reinterpret_cast<ulonglong2*>(p1 + (q*JP + jp)*PS);
            ulonglong2* pwB = reinterpret_cast<ulonglong2*>(p1 + (q*JP + jp + 104)*PS);
#pragma unroll
            for (int rv = 0; rv < 4; rv++) {
                ulonglong2 vA; vA.x = acc[2*rv+0];   vA.y = acc[2*rv+1];   pwA[rv] = vA;
                ulonglong2 vB; vB.x = acc[8+2*rv+0]; vB.y = acc[8+2*rv+1]; pwB[rv] = vB;
            }
        }
        __syncthreads();

        // ---- slot U: update2(i) + update1(i+1), xs roll ----
        {
#pragma unroll
            for (int tsk = 0; tsk < 2; tsk++) {
                int n = un + tsk*26;
                float gi = (p2[(0*JP + 0*HP+n)*PS + ur] + p2[(1*JP + 0*HP+n)*PS + ur])
                         + (p2[(2*JP + 0*HP+n)*PS + ur] + p2[(3*JP + 0*HP+n)*PS + ur]) + b2s[0*HP+n];
                float gf = (p2[(0*JP + 1*HP+n)*PS + ur] + p2[(1*JP + 1*HP+n)*PS + ur])
                         + (p2[(2*JP + 1*HP+n)*PS + ur] + p2[(3*JP + 1*HP+n)*PS + ur]) + b2s[1*HP+n];
                float gg = (p2[(0*JP + 2*HP+n)*PS + ur] + p2[(1*JP + 2*HP+n)*PS + ur])
                         + (p2[(2*JP + 2*HP+n)*PS + ur] + p2[(3*JP + 2*HP+n)*PS + ur]) + b2s[2*HP+n];
                float go = (p2[(0*JP + 3*HP+n)*PS + ur] + p2[(1*JP + 3*HP+n)*PS + ur])
                         + (p2[(2*JP + 3*HP+n)*PS + ur] + p2[(3*JP + 3*HP+n)*PS + ur]) + b2s[3*HP+n];
                float c = tsk ? c2b : c2a;
                c = siga(gf)*c + siga(gi)*tanha(gg);
                if (tsk) c2b = c; else c2a = c;
                h2s[n*RR + ur] = siga(go)*tanha(c);
            }
#pragma unroll
            for (int tsk = 0; tsk < 2; tsk++) {
                int n = un + tsk*26;
                float gi = (p1[(0*JP + 0*HP+n)*PS + ur] + p1[(1*JP + 0*HP+n)*PS + ur])
                         + (p1[(2*JP + 0*HP+n)*PS + ur] + p1[(3*JP + 0*HP+n)*PS + ur]);
                float gf = (p1[(0*JP + 1*HP+n)*PS + ur] + p1[(1*JP + 1*HP+n)*PS + ur])
                         + (p1[(2*JP + 1*HP+n)*PS + ur] + p1[(3*JP + 1*HP+n)*PS + ur]);
                float gg = (p1[(0*JP + 2*HP+n)*PS + ur] + p1[(1*JP + 2*HP+n)*PS + ur])
                         + (p1[(2*JP + 2*HP+n)*PS + ur] + p1[(3*JP + 2*HP+n)*PS + ur]);
                float go = (p1[(0*JP + 3*HP+n)*PS + ur] + p1[(1*JP + 3*HP+n)*PS + ur])
                         + (p1[(2*JP + 3*HP+n)*PS + ur] + p1[(3*JP + 3*HP+n)*PS + ur]);
                float c = tsk ? c1b : c1a;
                c = siga(gf)*c + siga(gi)*tanha(gg);
                if (tsk) c1b = c; else c1a = c;
                h1s[n*RR + ur] = siga(go)*tanha(c);
            }
        }
        if (tid >= RR && tid < 2*RR && (i + 2) < TT) xs[tid - RR] = xnext;
        __syncthreads();
    }

    // epilogue: out(TT-1)
    if (tid < 32) {
        int r = tid & 15, hf = tid >> 4;
        float s = 0.f;
        const float* wb = wls + hf*26;
        const float* hb = h2s + hf*26*RR;
#pragma unroll
        for (int n = 0; n < 26; n++) s = fmaf(wb[n], hb[n*RR + r], s);
        s += __shfl_xor_sync(0xffffffffu, s, 16);
        if (hf == 0) out[(row0 + r)*TT + (TT - 1)] = s + blin;
    }
}

extern "C" void kernel_launch(void* const* d_in, const int* in_sizes, int n_in,
                              void* d_out, int out_size)
{
    const float* input = (const float*)d_in[0];
    const float* W_ih1 = (const float*)d_in[1];
    const float* W_hh1 = (const float*)d_in[2];
    const float* b_ih1 = (const float*)d_in[3];
    const float* b_hh1 = (const float*)d_in[4];
    const float* W_ih2 = (const float*)d_in[5];
    const float* W_hh2 = (const float*)d_in[6];
    const float* b_ih2 = (const float*)d_in[7];
    const float* b_hh2 = (const float*)d_in[8];
    const float* W_lin = (const float*)d_in[9];
    const float* b_lin = (const float*)d_in[10];
    float* out = (float*)d_out;

    const int smem_bytes = (832*PS*2 + HP*RR*2 + RR + HP + JP) * (int)sizeof(float);
    cudaFuncSetAttribute(lstm_kernel, cudaFuncAttributeMaxDynamicSharedMemorySize, smem_bytes);

    prep_kernel<<<64, 256>>>(W_ih1, W_hh1, b_ih1, b_hh1,
                             W_ih2, W_hh2, b_ih2, b_hh2, W_lin, b_lin);
    lstm_kernel<<<BB/RR, NT, smem_bytes>>>(input, out);
}

// round 17
// speedup vs baseline: 1.1006x; 1.1006x over previous
#include <cuda_runtime.h>

// Problem constants (fixed instance: B=2048, T=2048, H=51)
#define H_  51
#define HP  52          // padded hidden
#define JP  208         // 4*HP gate count
#define RR  16          // batch rows per CTA (two halves of 8)
#define NT  416         // threads per CTA (13 warps)
#define TT  2048
#define BB  2048
#define PS  12          // smem partial stride (8 payload + 4 pad)

// Repacked weights (device globals; prep kernel fills them each launch)
__device__ float g_W1p[HP*JP];   // [k][j] layer-1 W_hh
__device__ float g_W2a[HP*JP];   // [k][j] layer-2 W_ih
__device__ float g_W2b[HP*JP];   // [k][j] layer-2 W_hh
__device__ float g_b1[JP];
__device__ float g_wx[JP];
__device__ float g_b2[JP];
__device__ float g_wlin[HP];
__device__ float g_blin[1];

__global__ void prep_kernel(const float* __restrict__ W_ih1, const float* __restrict__ W_hh1,
                            const float* __restrict__ b_ih1, const float* __restrict__ b_hh1,
                            const float* __restrict__ W_ih2, const float* __restrict__ W_hh2,
                            const float* __restrict__ b_ih2, const float* __restrict__ b_hh2,
                            const float* __restrict__ W_lin, const float* __restrict__ b_lin)
{
    int stride = gridDim.x * blockDim.x;
    int i0 = blockIdx.x * blockDim.x + threadIdx.x;
    for (int idx = i0; idx < HP*JP; idx += stride) {
        int k = idx / JP, j = idx % JP;
        int g = j / HP, n = j % HP;
        bool v = (n < H_) && (k < H_);
        int ro = g*H_ + n;
        g_W1p[idx] = v ? W_hh1[ro*H_ + k] : 0.f;
        g_W2a[idx] = v ? W_ih2[ro*H_ + k] : 0.f;
        g_W2b[idx] = v ? W_hh2[ro*H_ + k] : 0.f;
    }
    for (int j = i0; j < JP; j += stride) {
        int g = j / HP, n = j % HP;
        bool v = (n < H_);
        int ro = g*H_ + n;
        g_b1[j] = v ? (b_ih1[ro] + b_hh1[ro]) : 0.f;
        g_wx[j] = v ? W_ih1[ro] : 0.f;
        g_b2[j] = v ? (b_ih2[ro] + b_hh2[ro]) : 0.f;
    }
    for (int n = i0; n < HP; n += stride) g_wlin[n] = (n < H_) ? W_lin[n] : 0.f;
    if (i0 == 0) g_blin[0] = b_lin[0];
}

// HW tanh (single MUFU op)
__device__ __forceinline__ float tanha(float x) {
    float r; asm("tanh.approx.f32 %0, %1;" : "=f"(r) : "f"(x)); return r;
}
__device__ __forceinline__ float siga(float x) {
    return fmaf(0.5f, tanha(0.5f*x), 0.5f);
}

// ---- packed f32x2 helpers (PTX-only; ptxas won't auto-fuse) ----
__device__ __forceinline__ unsigned long long pk2(float w) {
    unsigned long long r;
    asm("mov.b64 %0, {%1, %1};" : "=l"(r) : "f"(w));
    return r;
}
__device__ __forceinline__ void fma2(unsigned long long& a, unsigned long long w, unsigned long long h) {
    asm("fma.rn.f32x2 %0, %1, %2, %3;" : "=l"(a) : "l"(w), "l"(h), "l"(a));
}

// phase-1 half-dot: G=2 (jp, jp+104), K=13 (chunk q), 8 rows of `half`
#define PHASE1_HALF(HALF, DST)                                                          \
    {                                                                                   \
        unsigned long long acc[8];                                                      \
        if (q == 0) {                                                                   \
            unsigned long long bpA = pk2(bias1a), wpA = pk2(wxa);                       \
            unsigned long long bpB = pk2(bias1b), wpB = pk2(wxb);                       \
            const ulonglong2* xv = reinterpret_cast<const ulonglong2*>(xs);             \
            _Pragma("unroll")                                                           \
            for (int rv = 0; rv < 2; rv++) {                                            \
                ulonglong2 x2 = xv[(HALF)*2 + rv];                                      \
                acc[2*rv+0] = bpA; fma2(acc[2*rv+0], wpA, x2.x);                        \
                acc[2*rv+1] = bpA; fma2(acc[2*rv+1], wpA, x2.y);                        \
                acc[4+2*rv+0] = bpB; fma2(acc[4+2*rv+0], wpB, x2.x);                    \
                acc[4+2*rv+1] = bpB; fma2(acc[4+2*rv+1], wpB, x2.y);                    \
            }                                                                           \
        } else {                                                                        \
            _Pragma("unroll")                                                           \
            for (int k = 0; k < 8; k++) acc[k] = 0ULL;                                  \
        }                                                                               \
        const ulonglong2* hb = reinterpret_cast<const ulonglong2*>(h1s + q*13*RR);      \
        _Pragma("unroll")                                                               \
        for (int kk = 0; kk < 13; kk++) {                                               \
            unsigned long long wA = pk2(w1[kk]);                                        \
            unsigned long long wB = pk2(w1[13 + kk]);                                   \
            _Pragma("unroll")                                                           \
            for (int rv = 0; rv < 2; rv++) {                                            \
                ulonglong2 h = hb[kk*4 + (HALF)*2 + rv];                                \
                fma2(acc[2*rv+0],   wA, h.x);                                           \
                fma2(acc[2*rv+1],   wA, h.y);                                           \
                fma2(acc[4+2*rv+0], wB, h.x);                                           \
                fma2(acc[4+2*rv+1], wB, h.y);                                           \
            }                                                                           \
        }                                                                               \
        ulonglong2* pwA = reinterpret_cast<ulonglong2*>((DST) + (q*JP + jp)*PS);        \
        ulonglong2* pwB = reinterpret_cast<ulonglong2*>((DST) + (q*JP + jp + 104)*PS);  \
        ulonglong2 vA0; vA0.x = acc[0]; vA0.y = acc[1]; pwA[0] = vA0;                   \
        ulonglong2 vA1; vA1.x = acc[2]; vA1.y = acc[3]; pwA[1] = vA1;                   \
        ulonglong2 vB0; vB0.x = acc[4]; vB0.y = acc[5]; pwB[0] = vB0;                   \
        ulonglong2 vB1; vB1.x = acc[6]; vB1.y = acc[7]; pwB[1] = vB1;                   \
    }

// phase-2 half-dot: G=2, K=26 (src, kh), 8 rows of `half`
#define PHASE2_HALF(HALF, DST)                                                          \
    {                                                                                   \
        unsigned long long acc[8];                                                      \
        _Pragma("unroll")                                                               \
        for (int k = 0; k < 8; k++) acc[k] = 0ULL;                                      \
        const ulonglong2* hb =                                                          \
            reinterpret_cast<const ulonglong2*>((src ? h2s : h1s) + kh*26*RR);          \
        _Pragma("unroll")                                                               \
        for (int kk = 0; kk < 26; kk++) {                                               \
            unsigned long long wA = pk2(w2[kk]);                                        \
            unsigned long long wB = pk2(w2[26 + kk]);                                   \
            _Pragma("unroll")                                                           \
            for (int rv = 0; rv < 2; rv++) {                                            \
                ulonglong2 h = hb[kk*4 + (HALF)*2 + rv];                                \
                fma2(acc[2*rv+0],   wA, h.x);                                           \
                fma2(acc[2*rv+1],   wA, h.y);                                           \
                fma2(acc[4+2*rv+0], wB, h.x);                                           \
                fma2(acc[4+2*rv+1], wB, h.y);                                           \
            }                                                                           \
        }                                                                               \
        ulonglong2* pwA = reinterpret_cast<ulonglong2*>((DST) + (q*JP + jp)*PS);        \
        ulonglong2* pwB = reinterpret_cast<ulonglong2*>((DST) + (q*JP + jp + 104)*PS);  \
        ulonglong2 vA0; vA0.x = acc[0]; vA0.y = acc[1]; pwA[0] = vA0;                   \
        ulonglong2 vA1; vA1.x = acc[2]; vA1.y = acc[3]; pwA[1] = vA1;                   \
        ulonglong2 vB0; vB0.x = acc[4]; vB0.y = acc[5]; pwB[0] = vB0;                   \
        ulonglong2 vB1; vB1.x = acc[6]; vB1.y = acc[7]; pwB[1] = vB1;                   \
    }

// layer-1 cell update for (cell un, row HALF*8+ur) from BUF; cell state C
#define UPDATE1_HALF(HALF, BUF, C)                                                      \
    {                                                                                   \
        int n = un;                                                                     \
        int r = ur;                                                                     \
        float gi = ((BUF)[(0*JP + 0*HP+n)*PS + r] + (BUF)[(1*JP + 0*HP+n)*PS + r])      \
                 + ((BUF)[(2*JP + 0*HP+n)*PS + r] + (BUF)[(3*JP + 0*HP+n)*PS + r]);     \
        float gf = ((BUF)[(0*JP + 1*HP+n)*PS + r] + (BUF)[(1*JP + 1*HP+n)*PS + r])      \
                 + ((BUF)[(2*JP + 1*HP+n)*PS + r] + (BUF)[(3*JP + 1*HP+n)*PS + r]);     \
        float gg = ((BUF)[(0*JP + 2*HP+n)*PS + r] + (BUF)[(1*JP + 2*HP+n)*PS + r])      \
                 + ((BUF)[(2*JP + 2*HP+n)*PS + r] + (BUF)[(3*JP + 2*HP+n)*PS + r]);     \
        float go = ((BUF)[(0*JP + 3*HP+n)*PS + r] + (BUF)[(1*JP + 3*HP+n)*PS + r])      \
                 + ((BUF)[(2*JP + 3*HP+n)*PS + r] + (BUF)[(3*JP + 3*HP+n)*PS + r]);     \
        (C) = siga(gf)*(C) + siga(gi)*tanha(gg);                                        \
        h1s[n*RR + (HALF)*8 + r] = siga(go)*tanha((C));                                 \
    }

// layer-2 cell update (+ bias) for (cell un, row HALF*8+ur) from BUF; state C
#define UPDATE2_HALF(HALF, BUF, C)                                                      \
    {                                                                                   \
        int n = un;                                                                     \
        int r = ur;                                                                     \
        float gi = ((BUF)[(0*JP + 0*HP+n)*PS + r] + (BUF)[(1*JP + 0*HP+n)*PS + r])      \
                 + ((BUF)[(2*JP + 0*HP+n)*PS + r] + (BUF)[(3*JP + 0*HP+n)*PS + r])      \
                 + b2s[0*HP+n];                                                         \
        float gf = ((BUF)[(0*JP + 1*HP+n)*PS + r] + (BUF)[(1*JP + 1*HP+n)*PS + r])      \
                 + ((BUF)[(2*JP + 1*HP+n)*PS + r] + (BUF)[(3*JP + 1*HP+n)*PS + r])      \
                 + b2s[1*HP+n];                                                         \
        float gg = ((BUF)[(0*JP + 2*HP+n)*PS + r] + (BUF)[(1*JP + 2*HP+n)*PS + r])      \
                 + ((BUF)[(2*JP + 2*HP+n)*PS + r] + (BUF)[(3*JP + 2*HP+n)*PS + r])      \
                 + b2s[2*HP+n];                                                         \
        float go = ((BUF)[(0*JP + 3*HP+n)*PS + r] + (BUF)[(1*JP + 3*HP+n)*PS + r])      \
                 + ((BUF)[(2*JP + 3*HP+n)*PS + r] + (BUF)[(3*JP + 3*HP+n)*PS + r])      \
                 + b2s[3*HP+n];                                                         \
        (C) = siga(gf)*(C) + siga(gi)*tanha(gg);                                        \
        h2s[n*RR + (HALF)*8 + r] = siga(go)*tanha((C));                                 \
    }

// output dot for 8 rows of `half` at time TIDX (warp 0, 4-way k split + shfl)
#define OUT_HALF(HALF, TIDX)                                                            \
    if (tid < 32) {                                                                     \
        int r8 = tid & 7, kq4 = tid >> 3;                                               \
        float s = 0.f;                                                                  \
        const float* wb = wls + kq4*13;                                                 \
        const float* hb = h2s + kq4*13*RR + (HALF)*8;                                   \
        _Pragma("unroll")                                                               \
        for (int n = 0; n < 13; n++) s = fmaf(wb[n], hb[n*RR + r8], s);                 \
        s += __shfl_xor_sync(0xffffffffu, s, 8);                                        \
        s += __shfl_xor_sync(0xffffffffu, s, 16);                                       \
        if (kq4 == 0) out[(row0 + (HALF)*8 + r8)*TT + (TIDX)] = s + blin;               \
    }

__global__ __launch_bounds__(NT, 1)
void lstm_kernel(const float* __restrict__ input, float* __restrict__ out)
{
    extern __shared__ float sm[];
    float* p1A = sm;                   // 832*PS each
    float* p1B = p1A + 832*PS;
    float* p2A = p1B + 832*PS;
    float* p2B = p2A + 832*PS;
    float* h1s = p2B + 832*PS;         // HP*RR  layout [k][r]
    float* h2s = h1s + HP*RR;
    float* xs  = h2s + HP*RR;          // RR
    float* wls = xs + RR;              // HP
    float* b2s = wls + HP;             // JP

    const int tid  = threadIdx.x;
    const int row0 = blockIdx.x * RR;

    // (q, jp) decomposition for both phases
    const int q   = tid / 104;              // 0..3
    const int jp  = tid - q*104;            // 0..103
    const int src = q >> 1;                 // phase2: 0 = W_ih2·h1, 1 = W_hh2·h2
    const int kh  = q & 1;                  // phase2 k-half
    // update task: one (cell, row-in-half) per thread per half
    const int un  = tid >> 3;               // 0..51
    const int ur  = tid & 7;                // 0..7

    // register-resident weights for both phases
    float w1[26];
#pragma unroll
    for (int kk = 0; kk < 13; kk++) {
        w1[kk]      = g_W1p[(q*13 + kk)*JP + jp];
        w1[13 + kk] = g_W1p[(q*13 + kk)*JP + jp + 104];
    }
    float w2[52];
    {
        const float* Ws = src ? g_W2b : g_W2a;
#pragma unroll
        for (int kk = 0; kk < 26; kk++) {
            w2[kk]      = Ws[(kh*26 + kk)*JP + jp];
            w2[26 + kk] = Ws[(kh*26 + kk)*JP + jp + 104];
        }
    }
    const float bias1a = g_b1[jp],  bias1b = g_b1[jp + 104];
    const float wxa    = g_wx[jp],  wxb    = g_wx[jp + 104];
    const float blin   = g_blin[0];

    // cell state: one per (layer, half)
    float c1A = 0.f, c1B = 0.f, c2A = 0.f, c2B = 0.f;

    for (int i = tid; i < HP*RR; i += NT) { h1s[i] = 0.f; h2s[i] = 0.f; }
    for (int i = tid; i < HP; i += NT) wls[i] = g_wlin[i];
    for (int i = tid; i < JP; i += NT) b2s[i] = g_b2[i];
    if (tid >= RR && tid < 2*RR) xs[tid - RR] = input[(row0 + tid - RR)*TT + 0];
    __syncthreads();

    // prologue: phase1_A(0)  (h1(-1)=0, so only bias/x part)
    PHASE1_HALF(0, p1A)
    __syncthreads();

    for (int i = 0; i < TT; i++) {
        float xnext = 0.f;
        if (tid >= RR && tid < 2*RR && (i + 1) < TT)
            xnext = __ldg(&input[(row0 + tid - RR)*TT + i + 1]);

        // S1: phase1_B(i) + update1_A(i)
        PHASE1_HALF(1, p1B)
        UPDATE1_HALF(0, p1A, c1A)
        __syncthreads();

        // S2: phase2_A(i) + update1_B(i) + out_A(i-1) + xs <- x(i+1)
        PHASE2_HALF(0, p2A)
        UPDATE1_HALF(1, p1B, c1B)
        if (i > 0) OUT_HALF(0, i - 1)
        if (tid >= RR && tid < 2*RR && (i + 1) < TT) xs[tid - RR] = xnext;
        __syncthreads();

        // S3: phase2_B(i) + update2_A(i) + out_B(i-1)
        PHASE2_HALF(1, p2B)
        UPDATE2_HALF(0, p2A, c2A)
        if (i > 0) OUT_HALF(1, i - 1)
        __syncthreads();

        // S4: phase1_A(i+1) + update2_B(i)
        PHASE1_HALF(0, p1A)
        UPDATE2_HALF(1, p2B, c2B)
        __syncthreads();
    }

    // epilogue: out(TT-1) for both halves
    OUT_HALF(0, TT - 1)
    OUT_HALF(1, TT - 1)
}

extern "C" void kernel_launch(void* const* d_in, const int* in_sizes, int n_in,
                              void* d_out, int out_size)
{
    const float* input = (const float*)d_in[0];
    const float* W_ih1 = (const float*)d_in[1];
    const float* W_hh1 = (const float*)d_in[2];
    const float* b_ih1 = (const float*)d_in[3];
    const float* b_hh1 = (const float*)d_in[4];
    const float* W_ih2 = (const float*)d_in[5];
    const float* W_hh2 = (const float*)d_in[6];
    const float* b_ih2 = (const float*)d_in[7];
    const float* b_hh2 = (const float*)d_in[8];
    const float* W_lin = (const float*)d_in[9];
    const float* b_lin = (const float*)d_in[10];
    float* out = (float*)d_out;

    const int smem_bytes = (4*832*PS + HP*RR*2 + RR + HP + JP) * (int)sizeof(float);
    cudaFuncSetAttribute(lstm_kernel, cudaFuncAttributeMaxDynamicSharedMemorySize, smem_bytes);

    prep_kernel<<<64, 256>>>(W_ih1, W_hh1, b_ih1, b_hh1,
                             W_ih2, W_hh2, b_ih2, b_hh2, W_lin, b_lin);
    lstm_kernel<<<BB/RR, NT, smem_bytes>>>(input, out);
}